// round 9
// baseline (speedup 1.0000x reference)
#include <cuda_runtime.h>
#include <math.h>
#include <stdint.h>

// Problem constants
#define SEQ   512
#define BATCH 64
#define HID   1024
#define NIN   512
#define NOUT  512
#define NCTA  128     // recurrence grid: 8 j-tiles(128) x 16 k-chunks(64)
#define NJT   8
#define NKC   16
#define BH    (BATCH * HID)

// Scratch (device globals). Layout of xi/h: [s][b][h]
__device__ float g_xi[(size_t)SEQ * BATCH * HID];
__device__ float g_h [(size_t)SEQ * BATCH * HID];
__device__ float g_part[2][NKC * BATCH * HID];    // parity double-buffered partials

// Dataflow counters (monotonic within a launch; reset node before each replay)
__device__ unsigned g_grp [NJT * 32];
__device__ unsigned g_done[NJT * 32];

__global__ void reset_barriers()
{
    if (threadIdx.x < NJT) {
        g_grp [threadIdx.x << 5] = 0;
        g_done[threadIdx.x << 5] = 0;
    }
}

__device__ __forceinline__ unsigned ld_acq(const unsigned* p)
{
    unsigned v;
    asm volatile("ld.acquire.gpu.global.u32 %0, [%1];" : "=r"(v) : "l"(p));
    return v;
}
__device__ __forceinline__ void arrive(unsigned* p)
{
    asm volatile("red.release.gpu.global.add.u32 [%0], 1;" :: "l"(p) : "memory");
}

__device__ __forceinline__ float tf32_hi(float a)
{
    uint32_t u;
    asm("cvt.rna.tf32.f32 %0, %1;" : "=r"(u) : "f"(a));
    return __uint_as_float(u);
}

// mma.sync m16n8k8 tf32 (sm_80+ baseline — works on compute_100 target)
#define MMA_TF32(c, a, b)                                                   \
    asm volatile("mma.sync.aligned.m16n8k8.row.col.f32.tf32.tf32.f32 "      \
        "{%0,%1,%2,%3}, {%4,%5,%6,%7}, {%8,%9}, {%0,%1,%2,%3};"             \
        : "+f"((c)[0]), "+f"((c)[1]), "+f"((c)[2]), "+f"((c)[3])            \
        : "r"((a)[0]), "r"((a)[1]), "r"((a)[2]), "r"((a)[3]),               \
          "r"((b)[0]), "r"((b)[1]))

// ---------------------------------------------------------------------------
// 3xTF32 mma.sync GEMM: C[M,N] = A[M,K] @ Bm[K,N] + bias.
// 128x128 block tile, K-tile 16, 8 warps (64x32 warp tiles).
// PERM=1: A row m=(b*512+s) -> C row (s*64+b)   [GEMM1: x->xi]
// PERM=2: A row m=(s*64+b)  -> C row (b*512+s)  [GEMM3: h->y]
// ---------------------------------------------------------------------------
template<int K, int N, int PERM>
__global__ __launch_bounds__(256) void gemm_mma(
    const float* __restrict__ A, const float* __restrict__ Bm,
    const float* __restrict__ bias, float* __restrict__ C)
{
    __shared__ float As_hi[16][132], As_lo[16][132];   // [k][m]
    __shared__ float Bs_hi[16][132], Bs_lo[16][132];   // [k][n]

    const int tid  = threadIdx.x;
    const int lane = tid & 31, wid = tid >> 5;
    const int gid  = lane >> 2, tig = lane & 3;
    const int wm   = wid & 1, wn = wid >> 1;           // 2 x 4 warp grid
    const int row0 = blockIdx.y * 128, col0 = blockIdx.x * 128;

    // global-load mapping
    const int a_row = tid >> 1, a_c8 = (tid & 1) << 3;   // A: row, 8-col group
    const int b_row = tid >> 5, b_c4 = (tid & 31) << 2;  // B: k row, col

    const float* Ap = A + (size_t)(row0 + a_row) * K + a_c8;
    const float* Bp = Bm + (size_t)b_row * N + col0 + b_c4;

    float4 pa0 = *(const float4*)Ap;
    float4 pa1 = *(const float4*)(Ap + 4);
    float4 pb0 = *(const float4*)Bp;
    float4 pb1 = *(const float4*)(Bp + (size_t)8 * N);

    float c[4][4][4] = {};                             // [mtile][ntile][reg]

    for (int k0 = 0; k0 < K; k0 += 16) {
        // ---- stage A transposed hi/lo ----
        {
            float va[8] = {pa0.x, pa0.y, pa0.z, pa0.w, pa1.x, pa1.y, pa1.z, pa1.w};
#pragma unroll
            for (int e = 0; e < 8; e++) {
                float hi = tf32_hi(va[e]);
                As_hi[a_c8 + e][a_row] = hi;
                As_lo[a_c8 + e][a_row] = va[e] - hi;
            }
        }
        // ---- stage B natural hi/lo ----
        {
            float vb0[4] = {pb0.x, pb0.y, pb0.z, pb0.w};
            float vb1[4] = {pb1.x, pb1.y, pb1.z, pb1.w};
#pragma unroll
            for (int e = 0; e < 4; e++) {
                float h0 = tf32_hi(vb0[e]);
                Bs_hi[b_row][b_c4 + e] = h0;
                Bs_lo[b_row][b_c4 + e] = vb0[e] - h0;
                float h1 = tf32_hi(vb1[e]);
                Bs_hi[b_row + 8][b_c4 + e] = h1;
                Bs_lo[b_row + 8][b_c4 + e] = vb1[e] - h1;
            }
        }
        __syncthreads();

        if (k0 + 16 < K) {
            pa0 = *(const float4*)(Ap + k0 + 16);
            pa1 = *(const float4*)(Ap + k0 + 20);
            pb0 = *(const float4*)(Bp + (size_t)(k0 + 16) * N);
            pb1 = *(const float4*)(Bp + (size_t)(k0 + 24) * N);
        }

#pragma unroll
        for (int kk = 0; kk < 16; kk += 8) {
            uint32_t ah[4][4], al[4][4], bh[4][2], bl[4][2];
#pragma unroll
            for (int i = 0; i < 4; i++) {
                const int m = wm * 64 + i * 16 + gid;
                ah[i][0] = __float_as_uint(As_hi[kk + tig    ][m]);
                ah[i][1] = __float_as_uint(As_hi[kk + tig    ][m + 8]);
                ah[i][2] = __float_as_uint(As_hi[kk + tig + 4][m]);
                ah[i][3] = __float_as_uint(As_hi[kk + tig + 4][m + 8]);
                al[i][0] = __float_as_uint(As_lo[kk + tig    ][m]);
                al[i][1] = __float_as_uint(As_lo[kk + tig    ][m + 8]);
                al[i][2] = __float_as_uint(As_lo[kk + tig + 4][m]);
                al[i][3] = __float_as_uint(As_lo[kk + tig + 4][m + 8]);
            }
#pragma unroll
            for (int j = 0; j < 4; j++) {
                const int n = wn * 32 + j * 8 + gid;
                bh[j][0] = __float_as_uint(Bs_hi[kk + tig    ][n]);
                bh[j][1] = __float_as_uint(Bs_hi[kk + tig + 4][n]);
                bl[j][0] = __float_as_uint(Bs_lo[kk + tig    ][n]);
                bl[j][1] = __float_as_uint(Bs_lo[kk + tig + 4][n]);
            }
#pragma unroll
            for (int i = 0; i < 4; i++)
#pragma unroll
                for (int j = 0; j < 4; j++) {
                    MMA_TF32(c[i][j], ah[i], bh[j]);
                    MMA_TF32(c[i][j], ah[i], bl[j]);
                    MMA_TF32(c[i][j], al[i], bh[j]);
                }
        }
        __syncthreads();
    }

    // ---- epilogue: bias + permuted row store ----
#pragma unroll
    for (int i = 0; i < 4; i++) {
        const int m_lo = row0 + wm * 64 + i * 16 + gid;
        const int m_hi = m_lo + 8;
        size_t r_lo, r_hi;
        if (PERM == 1) {
            r_lo = (size_t)((m_lo & 511) * 64 + (m_lo >> 9));
            r_hi = (size_t)((m_hi & 511) * 64 + (m_hi >> 9));
        } else {
            r_lo = (size_t)((m_lo & 63) * 512 + (m_lo >> 6));
            r_hi = (size_t)((m_hi & 63) * 512 + (m_hi >> 6));
        }
#pragma unroll
        for (int j = 0; j < 4; j++) {
            const int col = col0 + wn * 32 + j * 8 + 2 * tig;
            const float b0 = bias[col], b1 = bias[col + 1];
            *(float2*)&C[r_lo * N + col] = make_float2(c[i][j][0] + b0, c[i][j][1] + b1);
            *(float2*)&C[r_hi * N + col] = make_float2(c[i][j][2] + b0, c[i][j][3] + b1);
        }
    }
}

// ---------------------------------------------------------------------------
// Persistent recurrence (unchanged from round 7 — proven at ~4.2ms)
// ---------------------------------------------------------------------------
__global__ __launch_bounds__(128) void rnn_recurrence(const float* __restrict__ Wh)
{
    __shared__ float As[16][68];
    __shared__ float Bs[64][128];

    const int tid = threadIdx.x;
    const int jt = blockIdx.x & 7;
    const int kc = blockIdx.x >> 3;
    const int col0 = jt << 7;
    const int kbase = kc << 6;
    const int tx = tid & 15, ty = tid >> 4;
    const int a_r = tid >> 1, a_k8 = (tid & 1) << 3;
    const int src = (kc >> 1) << 5;
    const int own = jt << 5;

#pragma unroll
    for (int i = 0; i < 16; i++) {
        int e4 = i * 128 + tid;
        int k = e4 >> 5, c = (e4 & 31) << 2;
        *(float4*)&Bs[k][c] = *(const float4*)&Wh[(size_t)(kbase + k) * HID + col0 + c];
    }

    {
        const int b = (kc << 2) + (tid >> 5);
        const int c = col0 + ((tid & 31) << 2);
        const size_t off = (size_t)b * HID + c;
        float4 v = *(const float4*)&g_xi[off];
        v.x = fmaxf(tanhf(v.x), 0.0f);
        v.y = fmaxf(tanhf(v.y), 0.0f);
        v.z = fmaxf(tanhf(v.z), 0.0f);
        v.w = fmaxf(tanhf(v.w), 0.0f);
        *(float4*)&g_h[off] = v;
    }
    __syncthreads();
    if (tid == 0) arrive(&g_done[own]);

    for (int t = 1; t < SEQ; t++) {
        if (tid == 0) {
            const unsigned target = (unsigned)(NKC * t);
            while (ld_acq(&g_done[src]) < target) {}
        }
        __syncthreads();

        const float* hprev = g_h + (size_t)(t - 1) * BH;
        float* part = g_part[t & 1];
        float acc[8][8] = {};

        const float* hrow = hprev + (size_t)a_r * HID + kbase + a_k8;
        float4 pa0 = *(const float4*)hrow;
        float4 pa1 = *(const float4*)(hrow + 4);

        for (int k0 = 0; k0 < 64; k0 += 16) {
            As[a_k8 + 0][a_r] = pa0.x;
            As[a_k8 + 1][a_r] = pa0.y;
            As[a_k8 + 2][a_r] = pa0.z;
            As[a_k8 + 3][a_r] = pa0.w;
            As[a_k8 + 4][a_r] = pa1.x;
            As[a_k8 + 5][a_r] = pa1.y;
            As[a_k8 + 6][a_r] = pa1.z;
            As[a_k8 + 7][a_r] = pa1.w;
            __syncthreads();
            if (k0 + 16 < 64) {
                pa0 = *(const float4*)(hrow + k0 + 16);
                pa1 = *(const float4*)(hrow + k0 + 20);
            }
#pragma unroll
            for (int kk = 0; kk < 16; kk++) {
                float4 a0 = *(const float4*)&As[kk][ty << 3];
                float4 a1 = *(const float4*)&As[kk][(ty << 3) + 4];
                float4 b0 = *(const float4*)&Bs[k0 + kk][tx << 3];
                float4 b1 = *(const float4*)&Bs[k0 + kk][(tx << 3) + 4];
                float av[8] = {a0.x, a0.y, a0.z, a0.w, a1.x, a1.y, a1.z, a1.w};
                float bv[8] = {b0.x, b0.y, b0.z, b0.w, b1.x, b1.y, b1.z, b1.w};
#pragma unroll
                for (int i = 0; i < 8; i++)
#pragma unroll
                    for (int j = 0; j < 8; j++)
                        acc[i][j] = fmaf(av[i], bv[j], acc[i][j]);
            }
            __syncthreads();
        }

#pragma unroll
        for (int i = 0; i < 8; i++) {
            const int b = (ty << 3) + i;
            float* pp = &part[(size_t)kc * BH + (size_t)b * HID + col0 + (tx << 3)];
            *(float4*)pp = make_float4(acc[i][0], acc[i][1], acc[i][2], acc[i][3]);
            *(float4*)(pp + 4) = make_float4(acc[i][4], acc[i][5], acc[i][6], acc[i][7]);
        }
        __syncthreads();

        if (tid == 0) {
            arrive(&g_grp[own]);
            const unsigned target = (unsigned)(NKC * t);
            while (ld_acq(&g_grp[own]) < target) {}
        }
        __syncthreads();

        {
            const int b = (kc << 2) + (tid >> 5);
            const int c = col0 + ((tid & 31) << 2);
            const size_t eo = (size_t)b * HID + c;
            const size_t off = (size_t)t * BH + eo;
            float4 v = *(const float4*)&g_xi[off];
#pragma unroll
            for (int q = 0; q < NKC; q++) {
                float4 p = *(const float4*)&part[(size_t)q * BH + eo];
                v.x += p.x; v.y += p.y; v.z += p.z; v.w += p.w;
            }
            v.x = fmaxf(tanhf(v.x), 0.0f);
            v.y = fmaxf(tanhf(v.y), 0.0f);
            v.z = fmaxf(tanhf(v.z), 0.0f);
            v.w = fmaxf(tanhf(v.w), 0.0f);
            *(float4*)&g_h[off] = v;
        }
        __syncthreads();
        if (tid == 0) arrive(&g_done[own]);
    }
}

// ---------------------------------------------------------------------------
extern "C" void kernel_launch(void* const* d_in, const int* in_sizes, int n_in,
                              void* d_out, int out_size)
{
    const float* x  = (const float*)d_in[0];
    const float* Wi = (const float*)d_in[1];
    const float* bi = (const float*)d_in[2];
    const float* Wh = (const float*)d_in[3];
    const float* Wo = (const float*)d_in[4];
    const float* bo = (const float*)d_in[5];
    float* out = (float*)d_out;

    void* p;
    cudaGetSymbolAddress(&p, g_xi);
    float* xi = (float*)p;
    cudaGetSymbolAddress(&p, g_h);
    float* hh = (float*)p;

    // 0) zero dataflow counters so every graph replay starts clean
    reset_barriers<<<1, 32>>>();

    // 1) xi[s][b][h] = x @ Wi + bi   (3xTF32 mma.sync)
    gemm_mma<NIN, HID, 1><<<dim3(HID / 128, (BATCH * SEQ) / 128), 256>>>(x, Wi, bi, xi);

    // 2) whole recurrence in one persistent kernel (dataflow sync inside)
    rnn_recurrence<<<NCTA, 128>>>(Wh);

    // 3) y[b][s][o] = h @ Wo + bo    (3xTF32 mma.sync)
    gemm_mma<HID, NOUT, 2><<<dim3(NOUT / 128, (BATCH * SEQ) / 128), 256>>>(hh, Wo, bo, out);
}

// round 10
// speedup vs baseline: 1.0564x; 1.0564x over previous
#include <cuda_runtime.h>
#include <math.h>
#include <stdint.h>

// Problem constants
#define SEQ   512
#define BATCH 64
#define HID   1024
#define NIN   512
#define NOUT  512
#define NCTA  128     // recurrence grid: 8 j-tiles(128) x 16 k-chunks(64)
#define NJT   8
#define NKC   16
#define BH    (BATCH * HID)

// Scratch (device globals). Layout of xi/h: [s][b][h]
__device__ float g_xi[(size_t)SEQ * BATCH * HID];
__device__ float g_h [(size_t)SEQ * BATCH * HID];
__device__ float g_part[2][NKC * BATCH * HID];    // parity double-buffered partials

// Dataflow counters (monotonic within a launch; reset node before each replay)
__device__ unsigned g_grp [NJT * 32];
__device__ unsigned g_done[NJT * 32];

__global__ void reset_barriers()
{
    if (threadIdx.x < NJT) {
        g_grp [threadIdx.x << 5] = 0;
        g_done[threadIdx.x << 5] = 0;
    }
}

__device__ __forceinline__ unsigned ld_acq(const unsigned* p)
{
    unsigned v;
    asm volatile("ld.acquire.gpu.global.u32 %0, [%1];" : "=r"(v) : "l"(p));
    return v;
}
__device__ __forceinline__ void arrive(unsigned* p)
{
    asm volatile("red.release.gpu.global.add.u32 [%0], 1;" :: "l"(p) : "memory");
}

__device__ __forceinline__ float tf32_hi(float a)
{
    uint32_t u;
    asm("cvt.rna.tf32.f32 %0, %1;" : "=r"(u) : "f"(a));
    return __uint_as_float(u);
}

// mma.sync m16n8k8 tf32 (sm_80+ baseline; fragment mapping validated round 9)
#define MMA_TF32(c, a, b)                                                   \
    asm volatile("mma.sync.aligned.m16n8k8.row.col.f32.tf32.tf32.f32 "      \
        "{%0,%1,%2,%3}, {%4,%5,%6,%7}, {%8,%9}, {%0,%1,%2,%3};"             \
        : "+f"((c)[0]), "+f"((c)[1]), "+f"((c)[2]), "+f"((c)[3])            \
        : "r"((a)[0]), "r"((a)[1]), "r"((a)[2]), "r"((a)[3]),               \
          "r"((b)[0]), "r"((b)[1]))

// ---------------------------------------------------------------------------
// 128x128x8 fp32 SGEMM with bias + output-row permutation (round-7 proven).
// PERM=1: A row m=(b*512+s) -> C row (s*64+b)   [GEMM1: x->xi]
// PERM=2: A row m=(s*64+b)  -> C row (b*512+s)  [GEMM3: h->y]
// ---------------------------------------------------------------------------
template<int K, int N, int PERM>
__global__ __launch_bounds__(256, 2) void gemm128(
    const float* __restrict__ A, const float* __restrict__ Bm,
    const float* __restrict__ bias, float* __restrict__ C)
{
    __shared__ float As[8][132];
    __shared__ float Bs[8][128];

    const int tid = threadIdx.x;
    const int tx = tid & 15, ty = tid >> 4;
    const int row0 = blockIdx.y * 128, col0 = blockIdx.x * 128;

    const int a_r = tid >> 1, a_k = (tid & 1) << 2;
    const int b_k = tid >> 5, b_c = (tid & 31) << 2;

    const float* Ap = A + (size_t)(row0 + a_r) * K + a_k;
    const float* Bp = Bm + (size_t)b_k * N + col0 + b_c;

    float4 ar = *(const float4*)Ap;
    float4 br = *(const float4*)Bp;

    float acc[8][8] = {};

    for (int k0 = 0; k0 < K; k0 += 8) {
        As[a_k + 0][a_r] = ar.x;
        As[a_k + 1][a_r] = ar.y;
        As[a_k + 2][a_r] = ar.z;
        As[a_k + 3][a_r] = ar.w;
        *(float4*)&Bs[b_k][b_c] = br;
        __syncthreads();
        if (k0 + 8 < K) {
            ar = *(const float4*)(Ap + k0 + 8);
            br = *(const float4*)(Bp + (size_t)(k0 + 8) * N);
        }
#pragma unroll
        for (int kk = 0; kk < 8; kk++) {
            float4 a0 = *(const float4*)&As[kk][ty << 2];
            float4 a1 = *(const float4*)&As[kk][(ty << 2) + 64];
            float4 b0 = *(const float4*)&Bs[kk][tx << 2];
            float4 b1 = *(const float4*)&Bs[kk][(tx << 2) + 64];
            float av[8] = {a0.x, a0.y, a0.z, a0.w, a1.x, a1.y, a1.z, a1.w};
            float bv[8] = {b0.x, b0.y, b0.z, b0.w, b1.x, b1.y, b1.z, b1.w};
#pragma unroll
            for (int i = 0; i < 8; i++)
#pragma unroll
                for (int j = 0; j < 8; j++)
                    acc[i][j] = fmaf(av[i], bv[j], acc[i][j]);
        }
        __syncthreads();
    }

    float4 bb0 = *(const float4*)&bias[col0 + (tx << 2)];
    float4 bb1 = *(const float4*)&bias[col0 + (tx << 2) + 64];
#pragma unroll
    for (int i = 0; i < 8; i++) {
        const int mloc = (i < 4) ? ((ty << 2) + i) : ((ty << 2) + i + 60);
        const int m = row0 + mloc;
        size_t r;
        if (PERM == 1)      r = (size_t)((m & 511) * 64 + (m >> 9));
        else if (PERM == 2) r = (size_t)((m & 63) * 512 + (m >> 6));
        else                r = (size_t)m;
        float* Cr = C + r * N + col0;
        float4 o0 = make_float4(acc[i][0] + bb0.x, acc[i][1] + bb0.y,
                                acc[i][2] + bb0.z, acc[i][3] + bb0.w);
        float4 o1 = make_float4(acc[i][4] + bb1.x, acc[i][5] + bb1.y,
                                acc[i][6] + bb1.z, acc[i][7] + bb1.w);
        *(float4*)(Cr + (tx << 2)) = o0;
        *(float4*)(Cr + (tx << 2) + 64) = o1;
    }
}

// ---------------------------------------------------------------------------
// Persistent recurrence with tensor-core phase A (3xTF32 mma.sync).
// CTA = (jt = bx&7 -> 128 cols, kc = bx>>3 -> 64 k's), 128 threads = 4 warps.
// Wh slice staged ONCE into fragment-ordered hi/lo smem (float4 per lane per
// (kstep,n-tile)) -> one LDS.128 per B-fragment. Per step: stage h chunk,
// warp computes 16 rows x 128 cols via 8 ksteps x 16 ntiles x 3 MMAs.
// Sync/phase-B identical to the proven round-7 kernel.
// ---------------------------------------------------------------------------
#define RNN_SMEM (65536 + 17408)    // Bfrag 8*16*32 float4 + hs[64][68]

__global__ __launch_bounds__(128) void rnn_recurrence(const float* __restrict__ Wh)
{
    extern __shared__ float dsm[];
    float4* Bfrag = (float4*)dsm;            // [ks 8][j8 16][lane 32] float4
    float*  hs    = dsm + 16384;             // hs[64][68]

    const int tid  = threadIdx.x;
    const int lane = tid & 31, wid = tid >> 5;
    const int gid  = lane >> 2, tig = lane & 3;
    const int jt = blockIdx.x & 7, kc = blockIdx.x >> 3;
    const int col0 = jt << 7, kbase = kc << 6;
    const int src = (kc >> 1) << 5, own = jt << 5;

    // One-time: fragment-ordered hi/lo Wh slice (amortized over 511 steps)
    for (int i = tid; i < 4096; i += 128) {
        const int l = i & 31, j8 = (i >> 5) & 15, ks = i >> 9;
        const int g = l >> 2, tg = l & 3;
        const int k = ks * 8 + tg;
        const int n = col0 + j8 * 8 + g;
        float b0 = Wh[(size_t)(kbase + k) * HID + n];
        float b1 = Wh[(size_t)(kbase + k + 4) * HID + n];
        float b0h = tf32_hi(b0), b1h = tf32_hi(b1);
        Bfrag[i] = make_float4(b0h, b1h, b0 - b0h, b1 - b1h);
    }

    // h_0 init on this CTA's phase-B slice: rows [4kc..+4), cols [128jt..+128)
    {
        const int b = (kc << 2) + (tid >> 5);
        const int c = col0 + ((tid & 31) << 2);
        const size_t off = (size_t)b * HID + c;
        float4 v = *(const float4*)&g_xi[off];
        v.x = fmaxf(tanhf(v.x), 0.0f);
        v.y = fmaxf(tanhf(v.y), 0.0f);
        v.z = fmaxf(tanhf(v.z), 0.0f);
        v.w = fmaxf(tanhf(v.w), 0.0f);
        *(float4*)&g_h[off] = v;
    }
    __syncthreads();
    if (tid == 0) arrive(&g_done[own]);

    const int m0 = (wid << 4) + gid;        // warp's row base within 64

    for (int t = 1; t < SEQ; t++) {
        // ---- A-wait: h(t-1) cols [64kc..+64) ready (producer group kc>>1) ----
        if (tid == 0) {
            const unsigned target = (unsigned)(NKC * t);
            while (ld_acq(&g_done[src]) < target) {}
        }
        __syncthreads();

        // ---- stage h(t-1)[64][64] chunk into hs (coalesced) ----
        const float* hprev = g_h + (size_t)(t - 1) * BH;
        {
            const int r = tid >> 1, cb = (tid & 1) << 5;
            const float* s = hprev + (size_t)r * HID + kbase + cb;
            float* d = hs + r * 68 + cb;
#pragma unroll
            for (int j = 0; j < 8; j++)
                *(float4*)(d + j * 4) = *(const float4*)(s + j * 4);
        }
        __syncthreads();

        // ---- phase A: 16x128 slab per warp, 3xTF32 mma.sync ----
        float c[16][4];
#pragma unroll
        for (int j = 0; j < 16; j++) {
            c[j][0] = 0.f; c[j][1] = 0.f; c[j][2] = 0.f; c[j][3] = 0.f;
        }

#pragma unroll
        for (int ks = 0; ks < 8; ks++) {
            const int kb = ks * 8 + tig;
            float a0 = hs[m0 * 68 + kb];
            float a1 = hs[(m0 + 8) * 68 + kb];
            float a2 = hs[m0 * 68 + kb + 4];
            float a3 = hs[(m0 + 8) * 68 + kb + 4];
            uint32_t ah[4], al[4];
            float h;
            h = tf32_hi(a0); ah[0] = __float_as_uint(h); al[0] = __float_as_uint(a0 - h);
            h = tf32_hi(a1); ah[1] = __float_as_uint(h); al[1] = __float_as_uint(a1 - h);
            h = tf32_hi(a2); ah[2] = __float_as_uint(h); al[2] = __float_as_uint(a2 - h);
            h = tf32_hi(a3); ah[3] = __float_as_uint(h); al[3] = __float_as_uint(a3 - h);

            const float4* bp = Bfrag + (size_t)(ks * 16) * 32 + lane;
#pragma unroll
            for (int j8 = 0; j8 < 16; j8++) {
                float4 bf = bp[j8 * 32];
                uint32_t bh[2] = {__float_as_uint(bf.x), __float_as_uint(bf.y)};
                uint32_t bl[2] = {__float_as_uint(bf.z), __float_as_uint(bf.w)};
                MMA_TF32(c[j8], ah, bh);
                MMA_TF32(c[j8], ah, bl);
                MMA_TF32(c[j8], al, bh);
            }
        }

        // ---- store partials from fragments ----
        float* part = g_part[t & 1] + (size_t)kc * BH;
#pragma unroll
        for (int j8 = 0; j8 < 16; j8++) {
            float* pp = part + (size_t)m0 * HID + col0 + j8 * 8 + 2 * tig;
            *(float2*)pp = make_float2(c[j8][0], c[j8][1]);
            *(float2*)(pp + 8 * HID) = make_float2(c[j8][2], c[j8][3]);
        }
        __syncthreads();

        // ---- group arrive + wait (16 CTAs sharing this jt) ----
        if (tid == 0) {
            arrive(&g_grp[own]);
            const unsigned target = (unsigned)(NKC * t);
            while (ld_acq(&g_grp[own]) < target) {}
        }
        __syncthreads();

        // ---- phase B: reduce own 4-row slice, tanh, relu -> h_t (fp32) ----
        {
            const int b = (kc << 2) + (tid >> 5);
            const int cc = col0 + ((tid & 31) << 2);
            const size_t eo = (size_t)b * HID + cc;
            const size_t off = (size_t)t * BH + eo;
            float4 v = *(const float4*)&g_xi[off];
            const float* pt = g_part[t & 1];
#pragma unroll
            for (int q = 0; q < NKC; q++) {
                float4 p = *(const float4*)&pt[(size_t)q * BH + eo];
                v.x += p.x; v.y += p.y; v.z += p.z; v.w += p.w;
            }
            v.x = fmaxf(tanhf(v.x), 0.0f);
            v.y = fmaxf(tanhf(v.y), 0.0f);
            v.z = fmaxf(tanhf(v.z), 0.0f);
            v.w = fmaxf(tanhf(v.w), 0.0f);
            *(float4*)&g_h[off] = v;
        }
        __syncthreads();
        if (tid == 0) arrive(&g_done[own]);
    }
}

// ---------------------------------------------------------------------------
extern "C" void kernel_launch(void* const* d_in, const int* in_sizes, int n_in,
                              void* d_out, int out_size)
{
    const float* x  = (const float*)d_in[0];
    const float* Wi = (const float*)d_in[1];
    const float* bi = (const float*)d_in[2];
    const float* Wh = (const float*)d_in[3];
    const float* Wo = (const float*)d_in[4];
    const float* bo = (const float*)d_in[5];
    float* out = (float*)d_out;

    void* p;
    cudaGetSymbolAddress(&p, g_xi);
    float* xi = (float*)p;
    cudaGetSymbolAddress(&p, g_h);
    float* hh = (float*)p;

    cudaFuncSetAttribute(rnn_recurrence,
                         cudaFuncAttributeMaxDynamicSharedMemorySize, RNN_SMEM);

    // 0) zero dataflow counters so every graph replay starts clean
    reset_barriers<<<1, 32>>>();

    // 1) xi[s][b][h] = x @ Wi + bi   (fp32, ~roofline)
    gemm128<NIN, HID, 1><<<dim3(HID / 128, (BATCH * SEQ) / 128), 256>>>(x, Wi, bi, xi);

    // 2) whole recurrence in one persistent kernel (tensor-core phase A)
    rnn_recurrence<<<NCTA, 128, RNN_SMEM>>>(Wh);

    // 3) y[b][s][o] = h @ Wo + bo    (fp32, ~roofline)
    gemm128<HID, NOUT, 2><<<dim3(NOUT / 128, (BATCH * SEQ) / 128), 256>>>(hh, Wo, bo, out);
}